// round 1
// baseline (speedup 1.0000x reference)
#include <cuda_runtime.h>
#include <math.h>

#define TT 128
#define HH 64
#define WW 64
#define HW 4096

// ---------------- scratch (device globals: allocation-free rule) ----------------
__device__ float g_ys1[TT * 32 * HW];          // layer-1 hidden sequence (64 MB)
__device__ float g_ys2[TT * 64 * HW];          // layer-2 hidden sequence (128 MB)
__device__ float g_c1[32 * HW];
__device__ float g_c2[64 * HW];
__device__ float g_zero[64 * HW];              // zero-initialized at module load, never written
__device__ float g_wr1[4 * 40 * 9 * 32];       // reshaped w1: [coblk=4][ci_pad=40][tap=9][g=4][co=8]
__device__ float g_wr2[8 * 96 * 9 * 32];       // reshaped w2: [coblk=8][ci=96][tap=9][g=4][co=8]

__device__ __forceinline__ float sigf(float x) { return 1.0f / (1.0f + expf(-x)); }

// ---------------- zero the cell states (needed every launch: graph replays) -----
__global__ void zero_c_kernel() {
    int i = blockIdx.x * blockDim.x + threadIdx.x;
    if (i < 32 * HW) g_c1[i] = 0.0f;
    if (i < 64 * HW) g_c2[i] = 0.0f;
}

// ---------------- weight reshape: w[4*CHID][TOTC][3][3] -> per-block layout -----
template <int CHID, int TOTC, int TOTC_PAD>
__global__ void reshape_w_kernel(const float* __restrict__ w, float* __restrict__ wr) {
    const int n = (CHID / 8) * TOTC_PAD * 9 * 4 * 8;
    for (int i = blockIdx.x * blockDim.x + threadIdx.x; i < n; i += gridDim.x * blockDim.x) {
        int col  = i & 7;
        int g    = (i >> 3) & 3;
        int tap  = (i >> 5) % 9;
        int rest = i / 288;                 // 288 = 9*4*8
        int ci   = rest % TOTC_PAD;
        int cb   = rest / TOTC_PAD;
        float v = 0.0f;
        if (ci < TOTC) v = w[((g * CHID + cb * 8 + col) * TOTC + ci) * 9 + tap];
        wr[i] = v;
    }
}

// ---------------- fused ConvLSTM step --------------------------------------------
// Block: 128 threads; tile = 4 rows x 64 cols pixels, 8 output channels (x4 gates).
// Thread: 4 px (contig x) x 4 co x 4 gates = 64 accumulators.
template <int CIN, int CHID, int NCHUNK>     // padded in-channels = NCHUNK*8
__global__ void __launch_bounds__(128) step_kernel(
    const float* __restrict__ x,     // [CIN][H][W]
    const float* __restrict__ hin,   // [CHID][H][W]
    float* __restrict__ hout,        // [CHID][H][W]
    float* __restrict__ c,           // [CHID][H][W], in/out
    const float* __restrict__ wr,    // [CHID/8][NCHUNK*8][9][4][8]
    const float* __restrict__ b)     // [4*CHID]
{
    constexpr int TOTC = CIN + CHID;
    __shared__ __align__(16) float psm[8][6][68];     // 8 ci x (4 rows + halo) x (64 + halo, padded)
    __shared__ __align__(16) float wsm[8][9][4][8];

    const int tid     = threadIdx.x;
    const int co_half = tid >> 6;          // 0..1 -> which 4-co subset
    const int pid     = tid & 63;
    const int row     = pid >> 4;          // 0..3
    const int x0      = (pid & 15) << 2;   // 0,4,...,60

    const int co_blk = blockIdx.x >> 4;
    const int y0     = (blockIdx.x & 15) << 2;

    float acc[4][4][4];                    // [gate][co][px]
    #pragma unroll
    for (int g = 0; g < 4; g++)
        #pragma unroll
        for (int o = 0; o < 4; o++)
            #pragma unroll
            for (int j = 0; j < 4; j++) acc[g][o][j] = 0.0f;

    const float* wblk = wr + (size_t)co_blk * (NCHUNK * 8 * 9 * 32);

    for (int ch = 0; ch < NCHUNK; ch++) {
        // stage weights: 2304 contiguous floats
        {
            const float* src = wblk + ch * 2304;
            float* dst = &wsm[0][0][0][0];
            for (int i = tid; i < 2304; i += 128) dst[i] = src[i];
        }
        // stage input patch: 8 ci x 6 rows x 66 cols (zero-padded halo)
        for (int i = tid; i < 8 * 6 * 66; i += 128) {
            int col = i % 66;
            int r   = (i / 66) % 6;
            int ci  = i / 396;
            int cig = ch * 8 + ci;
            int y   = y0 - 1 + r;
            int xx  = col - 1;
            float v = 0.0f;
            if ((unsigned)y < HH && (unsigned)xx < WW) {
                if (cig < CIN)       v = x[cig * HW + y * WW + xx];
                else if (cig < TOTC) v = hin[(cig - CIN) * HW + y * WW + xx];
            }
            psm[ci][r][col] = v;
        }
        __syncthreads();

        #pragma unroll 2
        for (int ci = 0; ci < 8; ci++) {
            float seg[3][6];
            #pragma unroll
            for (int k = 0; k < 3; k++) {
                const float* p = &psm[ci][row + k][x0];
                float4 v4 = *(const float4*)p;
                seg[k][0] = v4.x; seg[k][1] = v4.y; seg[k][2] = v4.z; seg[k][3] = v4.w;
                seg[k][4] = p[4]; seg[k][5] = p[5];
            }
            #pragma unroll
            for (int ky = 0; ky < 3; ky++) {
                #pragma unroll
                for (int kx = 0; kx < 3; kx++) {
                    const int tap = ky * 3 + kx;
                    #pragma unroll
                    for (int g = 0; g < 4; g++) {
                        float4 wv = *(const float4*)&wsm[ci][tap][g][co_half * 4];
                        #pragma unroll
                        for (int j = 0; j < 4; j++) {
                            float pv = seg[ky][kx + j];
                            acc[g][0][j] += wv.x * pv;
                            acc[g][1][j] += wv.y * pv;
                            acc[g][2][j] += wv.z * pv;
                            acc[g][3][j] += wv.w * pv;
                        }
                    }
                }
            }
        }
        __syncthreads();
    }

    // epilogue: bias + gates + state update
    const int y = y0 + row;
    #pragma unroll
    for (int o = 0; o < 4; o++) {
        const int cog = co_blk * 8 + co_half * 4 + o;
        const float bi = b[0 * CHID + cog];
        const float bf = b[1 * CHID + cog];
        const float bo = b[2 * CHID + cog];
        const float bg = b[3 * CHID + cog];
        float* cptr = c    + cog * HW + y * WW + x0;
        float* hptr = hout + cog * HW + y * WW + x0;
        float4 cold = *(const float4*)cptr;
        float cv[4], hv[4];
        const float* co_ = (const float*)&cold;
        #pragma unroll
        for (int j = 0; j < 4; j++) {
            float iv = sigf(acc[0][o][j] + bi);
            float fv = sigf(acc[1][o][j] + bf);
            float ov = sigf(acc[2][o][j] + bo);
            float gv = tanhf(acc[3][o][j] + bg);
            float cn = fv * co_[j] + iv * gv;
            cv[j] = cn;
            hv[j] = ov * tanhf(cn);
        }
        *(float4*)cptr = make_float4(cv[0], cv[1], cv[2], cv[3]);
        *(float4*)hptr = make_float4(hv[0], hv[1], hv[2], hv[3]);
    }
}

// ---------------- FC head: pose[t][j] = <ys2[t], fc_w[j]> + fc_b[j] -------------
__global__ void fc_kernel(const float* __restrict__ ys2, const float* __restrict__ fcw,
                          const float* __restrict__ fcb, float* __restrict__ out) {
    const int t = blockIdx.y;
    const int j = blockIdx.x;
    const float* a = ys2 + (size_t)t * 64 * HW;
    const float* w = fcw + (size_t)j * 64 * HW;
    float s = 0.0f;
    const int n = 64 * HW;
    for (int i = threadIdx.x * 4; i < n; i += blockDim.x * 4) {
        float4 av = *(const float4*)(a + i);
        float4 bv = *(const float4*)(w + i);
        s += av.x * bv.x + av.y * bv.y + av.z * bv.z + av.w * bv.w;
    }
    __shared__ float red[32];
    for (int off = 16; off; off >>= 1) s += __shfl_down_sync(0xffffffffu, s, off);
    if ((threadIdx.x & 31) == 0) red[threadIdx.x >> 5] = s;
    __syncthreads();
    if (threadIdx.x < 32) {
        s = (threadIdx.x < (blockDim.x >> 5)) ? red[threadIdx.x] : 0.0f;
        for (int off = 16; off; off >>= 1) s += __shfl_down_sync(0xffffffffu, s, off);
        if (threadIdx.x == 0) out[t * 6 + j] = s + fcb[j];
    }
}

// ---------------- final state copy-out ------------------------------------------
// d_out layout: pose[128*6] | h1[32*HW] | c1[32*HW] | h2[64*HW] | c2[64*HW]
__global__ void copy_out_kernel(float* __restrict__ out) {
    const int i = blockIdx.x * blockDim.x + threadIdx.x;
    float* o = out + TT * 6;
    if (i < 32 * HW) {
        o[i]             = g_ys1[127 * 32 * HW + i];   // h1 final
        o[32 * HW + i]   = g_c1[i];                    // c1 final
    }
    if (i < 64 * HW) {
        o[64 * HW + i]            = g_ys2[(size_t)127 * 64 * HW + i];  // h2 final
        o[64 * HW + 64 * HW + i]  = g_c2[i];                            // c2 final
    }
}

// ---------------- launch ---------------------------------------------------------
extern "C" void kernel_launch(void* const* d_in, const int* in_sizes, int n_in,
                              void* d_out, int out_size) {
    const float* input = (const float*)d_in[0];
    const float* w1    = (const float*)d_in[1];
    const float* b1    = (const float*)d_in[2];
    const float* w2    = (const float*)d_in[3];
    const float* b2    = (const float*)d_in[4];
    const float* fcw   = (const float*)d_in[5];
    const float* fcb   = (const float*)d_in[6];
    float* out = (float*)d_out;

    float *ys1, *ys2, *c1, *c2, *zero, *wr1, *wr2;
    cudaGetSymbolAddress((void**)&ys1,  g_ys1);
    cudaGetSymbolAddress((void**)&ys2,  g_ys2);
    cudaGetSymbolAddress((void**)&c1,   g_c1);
    cudaGetSymbolAddress((void**)&c2,   g_c2);
    cudaGetSymbolAddress((void**)&zero, g_zero);
    cudaGetSymbolAddress((void**)&wr1,  g_wr1);
    cudaGetSymbolAddress((void**)&wr2,  g_wr2);

    zero_c_kernel<<<1024, 256>>>();
    reshape_w_kernel<32, 35, 40><<<64, 256>>>(w1, wr1);
    reshape_w_kernel<64, 96, 96><<<128, 256>>>(w2, wr2);

    // layer 1: CIN=3, CHID=32 -> 4 co-blocks x 16 row-blocks = 64 blocks
    for (int t = 0; t < TT; t++) {
        const float* hin = t ? (ys1 + (size_t)(t - 1) * 32 * HW) : zero;
        step_kernel<3, 32, 5><<<64, 128>>>(input + (size_t)t * 3 * HW, hin,
                                           ys1 + (size_t)t * 32 * HW, c1, wr1, b1);
    }
    // layer 2: CIN=32, CHID=64 -> 8 co-blocks x 16 row-blocks = 128 blocks
    for (int t = 0; t < TT; t++) {
        const float* hin = t ? (ys2 + (size_t)(t - 1) * 64 * HW) : zero;
        step_kernel<32, 64, 12><<<128, 128>>>(ys1 + (size_t)t * 32 * HW, hin,
                                              ys2 + (size_t)t * 64 * HW, c2, wr2, b2);
    }

    dim3 fg(6, TT);
    fc_kernel<<<fg, 256>>>(ys2, fcw, fcb, out);
    copy_out_kernel<<<1024, 256>>>(out);
}

// round 2
// speedup vs baseline: 2.4479x; 2.4479x over previous
#include <cuda_runtime.h>
#include <math.h>

#define TT 128
#define HH 64
#define WW 64
#define HW 4096

// ---------------- scratch (device globals: allocation-free rule) ----------------
__device__ float g_ys1[TT * 32 * HW];           // layer-1 hidden sequence (64 MB)
__device__ float g_ys2[TT * 64 * HW];           // layer-2 hidden sequence (128 MB)
__device__ float g_z1 [TT * 128 * HW];          // layer-1 x-part gate pre-activations (256 MB)
__device__ float g_z2 [TT * 256 * HW];          // layer-2 x-part gate pre-activations (512 MB)
__device__ float g_c1[32 * HW];
__device__ float g_c2[64 * HW];
__device__ float g_zero[64 * HW];               // zero at load, never written
__device__ float g_wx1[4 * 8  * 288];           // [coblk][ci_pad][tap9][g4][co8]
__device__ float g_wh1[4 * 32 * 288];
__device__ float g_wx2[8 * 32 * 288];
__device__ float g_wh2[8 * 64 * 288];

__device__ __forceinline__ float sigf(float x) { return 1.0f / (1.0f + expf(-x)); }

// packed f32x2 helpers (sm_103a FFMA2 path — PTX-only)
__device__ __forceinline__ unsigned long long splat2(float v) {
    unsigned long long d;
    asm("mov.b64 %0, {%1, %1};" : "=l"(d) : "f"(v));
    return d;
}
__device__ __forceinline__ void ffma2(unsigned long long& d, unsigned long long a, unsigned long long b) {
    asm("fma.rn.f32x2 %0, %1, %2, %0;" : "+l"(d) : "l"(a), "l"(b));
}
__device__ __forceinline__ float2 up2(unsigned long long v) {
    float2 f;
    asm("mov.b64 {%0, %1}, %2;" : "=f"(f.x), "=f"(f.y) : "l"(v));
    return f;
}

// ---------------- zero the cell states (graph replays re-run this) ---------------
__global__ void zero_c_kernel() {
    int i = blockIdx.x * blockDim.x + threadIdx.x;
    if (i < 32 * HW) g_c1[i] = 0.0f;
    if (i < 64 * HW) g_c2[i] = 0.0f;
}

// ------- weight reshape: w[4*CHID][TOTC][9] slice ci in [CI0,CI0+CIC) ------------
// output layout: [coblk][ci<CIPAD][tap9][g4][co8]
template <int CHID, int TOTC, int CI0, int CIC, int CIPAD>
__global__ void reshape_kernel(const float* __restrict__ w, float* __restrict__ wr) {
    const int n = (CHID / 8) * CIPAD * 288;
    for (int i = blockIdx.x * blockDim.x + threadIdx.x; i < n; i += gridDim.x * blockDim.x) {
        int co   = i & 7;
        int g    = (i >> 3) & 3;
        int tap  = (i >> 5) % 9;
        int rest = i / 288;
        int ci   = rest % CIPAD;
        int cb   = rest / CIPAD;
        float v = 0.0f;
        if (ci < CIC) v = w[((g * CHID + cb * 8 + co) * TOTC + CI0 + ci) * 9 + tap];
        wr[i] = v;
    }
}

// ---------------- unified conv kernel (f32x2 packed) -----------------------------
// Block: 128 threads. Tile: ROWS rows x 64 cols x 8 out-co (x4 gates).
// tid>>6 = co_half (4 of the 8 co). Thread: 4 gates x 4 co (2 packed pairs) x PXT px.
// LSTM=false: out = conv + bias (z precompute), batched over T via blockIdx.z.
// LSTM=true : out = LSTM state update using precomputed z (launched per step).
template <int CINR, int NCHUNK, int CHID, int ROWS, int PXT, bool LSTM>
__global__ void __launch_bounds__(128) conv_kernel(
    const float* __restrict__ xin, long xts,       // input [CINR][HW] (+ t*xts)
    const float* __restrict__ zin, long zts,       // LSTM: z [4*CHID][HW] (+ t*zts)
    float* __restrict__ outp, long ots,            // LSTM: hout ; else z out (+ t*ots)
    float* __restrict__ cst,                       // LSTM: cell state (in/out)
    const float* __restrict__ wr,
    const float* __restrict__ bias)                // !LSTM: bias [4*CHID]
{
    static_assert(ROWS == PXT, "tile geometry");
    constexpr int ROWBLK = 64 / ROWS;
    constexpr int GPR    = 64 / PXT;

    __shared__ __align__(16) float psm[8][ROWS + 2][68];
    __shared__ __align__(16) float wsm[8][9][4][8];

    const int tid     = threadIdx.x;
    const int co_half = tid >> 6;
    const int pid     = tid & 63;
    const int row     = pid / GPR;
    const int x0      = (pid % GPR) * PXT;

    const int co_blk = blockIdx.x / ROWBLK;
    const int y0     = (blockIdx.x % ROWBLK) * ROWS;
    const int t      = blockIdx.z;
    const float* x   = xin + (long)t * xts;

    unsigned long long acc[4][2][PXT];
    #pragma unroll
    for (int g = 0; g < 4; g++)
        #pragma unroll
        for (int p = 0; p < 2; p++)
            #pragma unroll
            for (int j = 0; j < PXT; j++) acc[g][p][j] = 0ull;

    const float* wblk = wr + (size_t)co_blk * (NCHUNK * 2304);

    for (int ch = 0; ch < NCHUNK; ch++) {
        // stage weights (contiguous)
        {
            const float* src = wblk + ch * 2304;
            float* dst = &wsm[0][0][0][0];
            for (int i = tid; i < 2304; i += 128) dst[i] = src[i];
        }
        // stage input patch: 8 ci x (ROWS+2) rows x 66 cols (halo, zero-padded)
        constexpr int NST = 8 * (ROWS + 2) * 66;
        for (int i = tid; i < NST; i += 128) {
            int col = i % 66;
            int r   = (i / 66) % (ROWS + 2);
            int ci  = i / (66 * (ROWS + 2));
            int cig = ch * 8 + ci;
            int y   = y0 - 1 + r;
            int xx  = col - 1;
            float v = 0.0f;
            if (cig < CINR && (unsigned)y < HH && (unsigned)xx < WW)
                v = x[(size_t)cig * HW + y * WW + xx];
            psm[ci][r][col] = v;
        }
        __syncthreads();

        #pragma unroll
        for (int ci = 0; ci < 8; ci++) {
            float seg[3][PXT + 2];
            #pragma unroll
            for (int k = 0; k < 3; k++)
                #pragma unroll
                for (int c2 = 0; c2 < PXT + 2; c2++)
                    seg[k][c2] = psm[ci][row + k][x0 + c2];

            #pragma unroll
            for (int ky = 0; ky < 3; ky++) {
                unsigned long long sp[PXT + 2];
                #pragma unroll
                for (int c2 = 0; c2 < PXT + 2; c2++) sp[c2] = splat2(seg[ky][c2]);
                #pragma unroll
                for (int kx = 0; kx < 3; kx++) {
                    #pragma unroll
                    for (int g = 0; g < 4; g++) {
                        const ulonglong2 wp =
                            *(const ulonglong2*)&wsm[ci][ky * 3 + kx][g][co_half * 4];
                        #pragma unroll
                        for (int j = 0; j < PXT; j++) {
                            ffma2(acc[g][0][j], wp.x, sp[kx + j]);
                            ffma2(acc[g][1][j], wp.y, sp[kx + j]);
                        }
                    }
                }
            }
        }
        __syncthreads();
    }

    // ---------------- epilogue ----------------
    const int y   = y0 + row;
    const int pos = y * WW + x0;

    if constexpr (!LSTM) {
        float* zo = outp + (long)t * ots;
        #pragma unroll
        for (int g = 0; g < 4; g++) {
            #pragma unroll
            for (int cl = 0; cl < 4; cl++) {
                const int co = co_blk * 8 + co_half * 4 + cl;
                const int chn = g * CHID + co;
                const float bv = bias[chn];
                float vals[PXT];
                #pragma unroll
                for (int j = 0; j < PXT; j++) {
                    float2 f = up2(acc[g][cl >> 1][j]);
                    vals[j] = ((cl & 1) ? f.y : f.x) + bv;
                }
                float* dst = zo + (size_t)chn * HW + pos;
                if constexpr (PXT == 4)
                    *(float4*)dst = make_float4(vals[0], vals[1], vals[2], vals[3]);
                else
                    *(float2*)dst = make_float2(vals[0], vals[1]);
            }
        }
    } else {
        const float* zp = zin + (long)t * zts;
        #pragma unroll
        for (int cl = 0; cl < 4; cl++) {
            const int co = co_blk * 8 + co_half * 4 + cl;
            float gv[4][PXT];
            #pragma unroll
            for (int g = 0; g < 4; g++) {
                float2 zl;
                if constexpr (PXT == 2)
                    zl = *(const float2*)(zp + ((size_t)g * CHID + co) * HW + pos);
                #pragma unroll
                for (int j = 0; j < PXT; j++) {
                    float2 f = up2(acc[g][cl >> 1][j]);
                    gv[g][j] = ((cl & 1) ? f.y : f.x) + ((j == 0) ? zl.x : zl.y);
                }
            }
            float* cp = cst  + (size_t)co * HW + pos;
            float* hp = outp + (size_t)co * HW + pos;
            float2 cold = *(const float2*)cp;
            float cv[2], hv[2];
            #pragma unroll
            for (int j = 0; j < 2; j++) {
                float iv = sigf(gv[0][j]);
                float fv = sigf(gv[1][j]);
                float ov = sigf(gv[2][j]);
                float gg = tanhf(gv[3][j]);
                float cn = fv * ((j == 0) ? cold.x : cold.y) + iv * gg;
                cv[j] = cn;
                hv[j] = ov * tanhf(cn);
            }
            *(float2*)cp = make_float2(cv[0], cv[1]);
            *(float2*)hp = make_float2(hv[0], hv[1]);
        }
    }
}

// ---------------- FC head --------------------------------------------------------
__global__ void fc_kernel(const float* __restrict__ ys2, const float* __restrict__ fcw,
                          const float* __restrict__ fcb, float* __restrict__ out) {
    const int t = blockIdx.y;
    const int j = blockIdx.x;
    const float* a = ys2 + (size_t)t * 64 * HW;
    const float* w = fcw + (size_t)j * 64 * HW;
    float s = 0.0f;
    const int n = 64 * HW;
    for (int i = threadIdx.x * 4; i < n; i += blockDim.x * 4) {
        float4 av = *(const float4*)(a + i);
        float4 bv = *(const float4*)(w + i);
        s += av.x * bv.x + av.y * bv.y + av.z * bv.z + av.w * bv.w;
    }
    __shared__ float red[32];
    for (int off = 16; off; off >>= 1) s += __shfl_down_sync(0xffffffffu, s, off);
    if ((threadIdx.x & 31) == 0) red[threadIdx.x >> 5] = s;
    __syncthreads();
    if (threadIdx.x < 32) {
        s = (threadIdx.x < (blockDim.x >> 5)) ? red[threadIdx.x] : 0.0f;
        for (int off = 16; off; off >>= 1) s += __shfl_down_sync(0xffffffffu, s, off);
        if (threadIdx.x == 0) out[t * 6 + j] = s + fcb[j];
    }
}

// ---------------- final state copy-out -------------------------------------------
__global__ void copy_out_kernel(float* __restrict__ out) {
    const int i = blockIdx.x * blockDim.x + threadIdx.x;
    float* o = out + TT * 6;
    if (i < 32 * HW) {
        o[i]           = g_ys1[127 * 32 * HW + i];
        o[32 * HW + i] = g_c1[i];
    }
    if (i < 64 * HW) {
        o[64 * HW + i]           = g_ys2[(size_t)127 * 64 * HW + i];
        o[64 * HW + 64 * HW + i] = g_c2[i];
    }
}

// ---------------- launch ---------------------------------------------------------
extern "C" void kernel_launch(void* const* d_in, const int* in_sizes, int n_in,
                              void* d_out, int out_size) {
    const float* input = (const float*)d_in[0];
    const float* w1    = (const float*)d_in[1];
    const float* b1    = (const float*)d_in[2];
    const float* w2    = (const float*)d_in[3];
    const float* b2    = (const float*)d_in[4];
    const float* fcw   = (const float*)d_in[5];
    const float* fcb   = (const float*)d_in[6];
    float* out = (float*)d_out;

    float *ys1, *ys2, *z1, *z2, *c1, *c2, *zero, *wx1, *wh1, *wx2, *wh2;
    cudaGetSymbolAddress((void**)&ys1,  g_ys1);
    cudaGetSymbolAddress((void**)&ys2,  g_ys2);
    cudaGetSymbolAddress((void**)&z1,   g_z1);
    cudaGetSymbolAddress((void**)&z2,   g_z2);
    cudaGetSymbolAddress((void**)&c1,   g_c1);
    cudaGetSymbolAddress((void**)&c2,   g_c2);
    cudaGetSymbolAddress((void**)&zero, g_zero);
    cudaGetSymbolAddress((void**)&wx1,  g_wx1);
    cudaGetSymbolAddress((void**)&wh1,  g_wh1);
    cudaGetSymbolAddress((void**)&wx2,  g_wx2);
    cudaGetSymbolAddress((void**)&wh2,  g_wh2);

    zero_c_kernel<<<1024, 256>>>();
    reshape_kernel<32, 35, 0,  3,  8><<<32,  256>>>(w1, wx1);
    reshape_kernel<32, 35, 3,  32, 32><<<64,  256>>>(w1, wh1);
    reshape_kernel<64, 96, 0,  32, 32><<<128, 256>>>(w2, wx2);
    reshape_kernel<64, 96, 32, 64, 64><<<256, 256>>>(w2, wh2);

    // layer-1 x-part for all T (batched): grid (4 co-blk x 16 row-blk, 1, T)
    conv_kernel<3, 1, 32, 4, 4, false><<<dim3(64, 1, TT), 128>>>(
        input, 3 * HW, nullptr, 0, z1, 128 * HW, nullptr, wx1, b1);

    // layer-1 serial h-part: grid 4 co-blk x 32 row-blk = 128
    for (int t = 0; t < TT; t++) {
        const float* hin = t ? (ys1 + (size_t)(t - 1) * 32 * HW) : zero;
        conv_kernel<32, 4, 32, 2, 2, true><<<128, 128>>>(
            hin, 0, z1 + (size_t)t * 128 * HW, 0,
            ys1 + (size_t)t * 32 * HW, 0, c1, wh1, nullptr);
    }

    // layer-2 x-part for all T (batched): grid (8 x 16, 1, T)
    conv_kernel<32, 4, 64, 4, 4, false><<<dim3(128, 1, TT), 128>>>(
        ys1, 32 * HW, nullptr, 0, z2, 256 * HW, nullptr, wx2, b2);

    // layer-2 serial h-part: grid 8 co-blk x 32 row-blk = 256
    for (int t = 0; t < TT; t++) {
        const float* hin = t ? (ys2 + (size_t)(t - 1) * 64 * HW) : zero;
        conv_kernel<64, 8, 64, 2, 2, true><<<256, 128>>>(
            hin, 0, z2 + (size_t)t * 256 * HW, 0,
            ys2 + (size_t)t * 64 * HW, 0, c2, wh2, nullptr);
    }

    dim3 fg(6, TT);
    fc_kernel<<<fg, 256>>>(ys2, fcw, fcb, out);
    copy_out_kernel<<<1024, 256>>>(out);
}

// round 6
// speedup vs baseline: 2.4632x; 1.0063x over previous
#include <cuda_runtime.h>
#include <math.h>

#define TT 128
#define HH 64
#define WW 64
#define HW 4096

// ---------------- scratch (device globals: allocation-free rule) ----------------
__device__ float g_ys1[TT * 32 * HW];           // layer-1 hidden sequence
__device__ float g_ys2[TT * 64 * HW];           // layer-2 hidden sequence
__device__ float g_z1 [TT * 128 * HW];          // layer-1 x-part preactivations
__device__ float g_c1[32 * HW];
__device__ float g_c2[64 * HW];
__device__ float g_zero[64 * HW];               // zero at load, never written
__device__ float g_wx1[4 * 8 * 288];            // COB=8: [coblk][ci][9][4][8]
__device__ float g_wh1[8 * 32 * 144];           // COB=4: [coblk][ci][9][4][4]
__device__ float g_wh2[16 * 96 * 144];          // COB=4, all 96 in-ch of layer 2

__device__ __forceinline__ float sigf(float x) { return 1.0f / (1.0f + expf(-x)); }

// packed f32x2 helpers (sm_103a FFMA2 — PTX-only)
__device__ __forceinline__ unsigned long long splat2(float v) {
    unsigned long long d;
    asm("mov.b64 %0, {%1, %1};" : "=l"(d) : "f"(v));
    return d;
}
__device__ __forceinline__ void ffma2(unsigned long long& d, unsigned long long a, unsigned long long b) {
    asm("fma.rn.f32x2 %0, %1, %2, %0;" : "+l"(d) : "l"(a), "l"(b));
}
__device__ __forceinline__ float2 up2(unsigned long long v) {
    float2 f;
    asm("mov.b64 {%0, %1}, %2;" : "=f"(f.x), "=f"(f.y) : "l"(v));
    return f;
}

// ---------------- zero the cell states (graph replays re-run this) ---------------
__global__ void zero_c_kernel() {
    int i = blockIdx.x * blockDim.x + threadIdx.x;
    if (i < 32 * HW) g_c1[i] = 0.0f;
    if (i < 64 * HW) g_c2[i] = 0.0f;
}

// ------- weight reshape: w[4*CHID][TOTC][9], ci slice -> [coblk][ci][9][4][COB] --
template <int CHID, int TOTC, int CI0, int CIC, int CIPAD, int COB>
__global__ void reshape_kernel(const float* __restrict__ w, float* __restrict__ wr) {
    const int n = (CHID / COB) * CIPAD * 36 * COB;
    for (int i = blockIdx.x * blockDim.x + threadIdx.x; i < n; i += gridDim.x * blockDim.x) {
        int co   = i % COB;
        int g    = (i / COB) & 3;
        int tap  = (i / (COB * 4)) % 9;
        int rest = i / (COB * 36);
        int ci   = rest % CIPAD;
        int cb   = rest / CIPAD;
        float v = 0.0f;
        if (ci < CIC) v = w[((g * CHID + cb * COB + co) * TOTC + CI0 + ci) * 9 + tap];
        wr[i] = v;
    }
}

// ---------------- batched x-part conv (COB=8, 4x4 tile, f32x2) -------------------
// used only for layer-1 z precompute over all T (blockIdx.z = t)
template <int CINR, int NCHUNK, int CHID>
__global__ void __launch_bounds__(128) zx_kernel(
    const float* __restrict__ xin, long xts,
    float* __restrict__ zout, long zts,
    const float* __restrict__ wr, const float* __restrict__ bias)
{
    __shared__ __align__(16) float psm[8][6][68];
    __shared__ __align__(16) float wsm[8][9][4][8];

    const int tid     = threadIdx.x;
    const int co_half = tid >> 6;
    const int pid     = tid & 63;
    const int row     = pid >> 4;
    const int x0      = (pid & 15) << 2;

    const int co_blk = blockIdx.x >> 4;
    const int y0     = (blockIdx.x & 15) << 2;
    const float* x   = xin + (long)blockIdx.z * xts;

    unsigned long long acc[4][2][4];
    #pragma unroll
    for (int g = 0; g < 4; g++)
        #pragma unroll
        for (int p = 0; p < 2; p++)
            #pragma unroll
            for (int j = 0; j < 4; j++) acc[g][p][j] = 0ull;

    const float* wblk = wr + (size_t)co_blk * (NCHUNK * 2304);

    for (int ch = 0; ch < NCHUNK; ch++) {
        {
            const float* src = wblk + ch * 2304;
            float* dst = &wsm[0][0][0][0];
            for (int i = tid; i < 2304; i += 128) dst[i] = src[i];
        }
        for (int i = tid; i < 8 * 6 * 66; i += 128) {
            int col = i % 66;
            int r   = (i / 66) % 6;
            int ci  = i / 396;
            int cig = ch * 8 + ci;
            int y   = y0 - 1 + r;
            int xx  = col - 1;
            float v = 0.0f;
            if (cig < CINR && (unsigned)y < HH && (unsigned)xx < WW)
                v = x[(size_t)cig * HW + y * WW + xx];
            psm[ci][r][col] = v;
        }
        __syncthreads();

        #pragma unroll
        for (int ci = 0; ci < 8; ci++) {
            float seg[3][6];
            #pragma unroll
            for (int k = 0; k < 3; k++)
                #pragma unroll
                for (int c2 = 0; c2 < 6; c2++) seg[k][c2] = psm[ci][row + k][x0 + c2];
            #pragma unroll
            for (int ky = 0; ky < 3; ky++) {
                unsigned long long sp[6];
                #pragma unroll
                for (int c2 = 0; c2 < 6; c2++) sp[c2] = splat2(seg[ky][c2]);
                #pragma unroll
                for (int kx = 0; kx < 3; kx++)
                    #pragma unroll
                    for (int g = 0; g < 4; g++) {
                        const ulonglong2 wp = *(const ulonglong2*)&wsm[ci][ky * 3 + kx][g][co_half * 4];
                        #pragma unroll
                        for (int j = 0; j < 4; j++) {
                            ffma2(acc[g][0][j], wp.x, sp[kx + j]);
                            ffma2(acc[g][1][j], wp.y, sp[kx + j]);
                        }
                    }
            }
        }
        __syncthreads();
    }

    const int pos = (y0 + row) * WW + x0;
    float* zo = zout + (long)blockIdx.z * zts;
    #pragma unroll
    for (int g = 0; g < 4; g++)
        #pragma unroll
        for (int cl = 0; cl < 4; cl++) {
            const int co  = co_blk * 8 + co_half * 4 + cl;
            const int chn = g * CHID + co;
            const float bv = bias[chn];
            float vals[4];
            #pragma unroll
            for (int j = 0; j < 4; j++) {
                float2 f = up2(acc[g][cl >> 1][j]);
                vals[j] = ((cl & 1) ? f.y : f.x) + bv;
            }
            *(float4*)(zo + (size_t)chn * HW + pos) = make_float4(vals[0], vals[1], vals[2], vals[3]);
        }
}

// ---------------- serial conv-LSTM core: COB=4, 2 rows x 64 cols tile ------------
// channels [0,CINA) from xa, [CINA,CINA+CINB) from xb. HAS_Z: gates = acc + z;
// else gates = acc + bias.
template <int CINA, int CINB, int NCHUNK, int CHID, bool HAS_Z>
__device__ __forceinline__ void conv_core(
    const float* __restrict__ xa, const float* __restrict__ xb,
    const float* __restrict__ zin, const float* __restrict__ bias,
    float* __restrict__ hout, float* __restrict__ cst,
    const float* __restrict__ wr, int blk, float* smem)
{
    float (*psm)[4][68] = (float(*)[4][68])smem;          // 8 x 4 x 68 = 2176
    float* wsm = smem + 2176;                              // 8 x 9 x 4 x 4 = 1152

    const int tid     = threadIdx.x;
    const int co_half = tid >> 6;           // 0..1 -> co pair within COB=4
    const int pid     = tid & 63;
    const int row     = pid >> 5;           // 0..1
    const int x0      = (pid & 31) << 1;    // 0,2,...,62

    const int co_blk = blk >> 5;
    const int y0     = (blk & 31) << 1;

    unsigned long long acc[4][2];           // [gate][px], packed pair over 2 co
    #pragma unroll
    for (int g = 0; g < 4; g++) { acc[g][0] = 0ull; acc[g][1] = 0ull; }

    const float* wblk = wr + (size_t)co_blk * (NCHUNK * 1152);

    for (int ch = 0; ch < NCHUNK; ch++) {
        {
            const float* src = wblk + ch * 1152;
            #pragma unroll
            for (int k = 0; k < 9; k++) wsm[tid + k * 128] = src[tid + k * 128];
        }
        for (int i = tid; i < 8 * 4 * 66; i += 128) {
            int col = i % 66;
            int r   = (i / 66) & 3;
            int ci  = i / 264;
            int cig = ch * 8 + ci;
            int y   = y0 - 1 + r;
            int xx  = col - 1;
            float v = 0.0f;
            if ((unsigned)y < HH && (unsigned)xx < WW) {
                if (cig < CINA)              v = xa[(size_t)cig * HW + y * WW + xx];
                else if (cig < CINA + CINB)  v = xb[(size_t)(cig - CINA) * HW + y * WW + xx];
            }
            psm[ci][r][col] = v;
        }
        __syncthreads();

        #pragma unroll
        for (int ci = 0; ci < 8; ci++) {
            #pragma unroll
            for (int ky = 0; ky < 3; ky++) {
                unsigned long long sp[4];
                #pragma unroll
                for (int c2 = 0; c2 < 4; c2++) sp[c2] = splat2(psm[ci][row + ky][x0 + c2]);
                #pragma unroll
                for (int kx = 0; kx < 3; kx++) {
                    const float* wb = wsm + ((ci * 9 + ky * 3 + kx) * 4) * 4 + co_half * 2;
                    #pragma unroll
                    for (int g = 0; g < 4; g++) {
                        const unsigned long long wv = *(const unsigned long long*)(wb + g * 4);
                        ffma2(acc[g][0], wv, sp[kx]);
                        ffma2(acc[g][1], wv, sp[kx + 1]);
                    }
                }
            }
        }
        __syncthreads();
    }

    const int pos = (y0 + row) * WW + x0;
    #pragma unroll
    for (int cl = 0; cl < 2; cl++) {
        const int co = co_blk * 4 + co_half * 2 + cl;
        float gv[4][2];
        #pragma unroll
        for (int g = 0; g < 4; g++) {
            float a0, a1;
            if constexpr (HAS_Z) {
                float2 zl = *(const float2*)(zin + ((size_t)g * CHID + co) * HW + pos);
                a0 = zl.x; a1 = zl.y;
            } else {
                a0 = a1 = bias[g * CHID + co];
            }
            float2 f0 = up2(acc[g][0]);
            float2 f1 = up2(acc[g][1]);
            gv[g][0] = (cl ? f0.y : f0.x) + a0;
            gv[g][1] = (cl ? f1.y : f1.x) + a1;
        }
        float* cp = cst  + (size_t)co * HW + pos;
        float* hp = hout + (size_t)co * HW + pos;
        float2 cold = *(const float2*)cp;
        float cv[2], hv[2];
        #pragma unroll
        for (int j = 0; j < 2; j++) {
            float iv = sigf(gv[0][j]);
            float fv = sigf(gv[1][j]);
            float ov = sigf(gv[2][j]);
            float gg = tanhf(gv[3][j]);
            float cn = fv * ((j == 0) ? cold.x : cold.y) + iv * gg;
            cv[j] = cn;
            hv[j] = ov * tanhf(cn);
        }
        *(float2*)cp = make_float2(cv[0], cv[1]);
        *(float2*)hp = make_float2(hv[0], hv[1]);
    }
}

// ---------------- per-slot fat kernel: L1h(t) blocks + L2full(t-1) blocks --------
__global__ void __launch_bounds__(128) slot_kernel(const float* __restrict__ b2, int t) {
    __shared__ __align__(16) float smem[3328];
    const int b = blockIdx.x;
    if (b < 256) {                                   // layer-1 h-step t
        if (t >= TT) return;
        const float* hin = t ? g_ys1 + (size_t)(t - 1) * 32 * HW : g_zero;
        conv_core<32, 0, 4, 32, true>(
            hin, nullptr, g_z1 + (size_t)t * 128 * HW, nullptr,
            g_ys1 + (size_t)t * 32 * HW, g_c1, g_wh1, b, smem);
    } else {                                         // layer-2 full step t-1
        if (t < 1) return;
        const int s = t - 1;
        const float* xa  = g_ys1 + (size_t)s * 32 * HW;
        const float* hin = s ? g_ys2 + (size_t)(s - 1) * 64 * HW : g_zero;
        conv_core<32, 64, 12, 64, false>(
            xa, hin, nullptr, b2,
            g_ys2 + (size_t)s * 64 * HW, g_c2, g_wh2, b - 256, smem);
    }
}

// ---------------- FC head --------------------------------------------------------
__global__ void fc_kernel(const float* __restrict__ ys2, const float* __restrict__ fcw,
                          const float* __restrict__ fcb, float* __restrict__ out) {
    const int t = blockIdx.y;
    const int j = blockIdx.x;
    const float* a = ys2 + (size_t)t * 64 * HW;
    const float* w = fcw + (size_t)j * 64 * HW;
    float s = 0.0f;
    const int n = 64 * HW;
    for (int i = threadIdx.x * 4; i < n; i += blockDim.x * 4) {
        float4 av = *(const float4*)(a + i);
        float4 bv = *(const float4*)(w + i);
        s += av.x * bv.x + av.y * bv.y + av.z * bv.z + av.w * bv.w;
    }
    __shared__ float red[32];
    for (int off = 16; off; off >>= 1) s += __shfl_down_sync(0xffffffffu, s, off);
    if ((threadIdx.x & 31) == 0) red[threadIdx.x >> 5] = s;
    __syncthreads();
    if (threadIdx.x < 32) {
        s = (threadIdx.x < (blockDim.x >> 5)) ? red[threadIdx.x] : 0.0f;
        for (int off = 16; off; off >>= 1) s += __shfl_down_sync(0xffffffffu, s, off);
        if (threadIdx.x == 0) out[t * 6 + j] = s + fcb[j];
    }
}

// ---------------- final state copy-out -------------------------------------------
__global__ void copy_out_kernel(float* __restrict__ out) {
    const int i = blockIdx.x * blockDim.x + threadIdx.x;
    float* o = out + TT * 6;
    if (i < 32 * HW) {
        o[i]           = g_ys1[127 * 32 * HW + i];
        o[32 * HW + i] = g_c1[i];
    }
    if (i < 64 * HW) {
        o[64 * HW + i]           = g_ys2[(size_t)127 * 64 * HW + i];
        o[64 * HW + 64 * HW + i] = g_c2[i];
    }
}

// ---------------- launch (single stream, no stream/event objects) ----------------
extern "C" void kernel_launch(void* const* d_in, const int* in_sizes, int n_in,
                              void* d_out, int out_size) {
    const float* input = (const float*)d_in[0];
    const float* w1    = (const float*)d_in[1];
    const float* b1    = (const float*)d_in[2];
    const float* w2    = (const float*)d_in[3];
    const float* b2    = (const float*)d_in[4];
    const float* fcw   = (const float*)d_in[5];
    const float* fcb   = (const float*)d_in[6];
    float* out = (float*)d_out;

    float *ys2, *z1, *wx1, *wh1, *wh2;
    cudaGetSymbolAddress((void**)&ys2, g_ys2);
    cudaGetSymbolAddress((void**)&z1,  g_z1);
    cudaGetSymbolAddress((void**)&wx1, g_wx1);
    cudaGetSymbolAddress((void**)&wh1, g_wh1);
    cudaGetSymbolAddress((void**)&wh2, g_wh2);

    zero_c_kernel<<<1024, 256>>>();
    reshape_kernel<32, 35, 0, 3,  8,  8><<<32,  256>>>(w1, wx1);
    reshape_kernel<32, 35, 3, 32, 32, 4><<<64,  256>>>(w1, wh1);
    reshape_kernel<64, 96, 0, 96, 96, 4><<<432, 256>>>(w2, wh2);

    // layer-1 x-part for all T (batched)
    zx_kernel<3, 1, 32><<<dim3(64, 1, TT), 128>>>(input, 3 * HW, z1, 128 * HW, wx1, b1);

    // interleaved serial chains: slot t = L1h(t) + L2full(t-1)
    for (int t = 0; t <= TT; t++)
        slot_kernel<<<768, 128>>>(b2, t);

    dim3 fg(6, TT);
    fc_kernel<<<fg, 256>>>(ys2, fcw, fcb, out);
    copy_out_kernel<<<1024, 256>>>(out);
}

// round 7
// speedup vs baseline: 3.5171x; 1.4278x over previous
#include <cuda_runtime.h>
#include <math.h>

#define TT 128
#define HH 64
#define WW 64
#define HW 4096

// ---------------- scratch (device globals: allocation-free rule) ----------------
__device__ float g_ys1[TT * 32 * HW];           // layer-1 hidden sequence
__device__ float g_ys2[TT * 64 * HW];           // layer-2 hidden sequence
__device__ float g_z1 [TT * 128 * HW];          // layer-1 x-part preactivations
__device__ float g_z2r[4 * 256 * HW];           // layer-2 x-part ring (4 steps)
__device__ float g_c1[32 * HW];
__device__ float g_c2[64 * HW];
__device__ float g_zero[64 * HW];               // zero at load, never written
__device__ float g_wx1[4 * 8  * 288];           // [coblk][ci][9][4][8]
__device__ float g_wh1[4 * 32 * 288];
__device__ float g_wx2[8 * 32 * 288];
__device__ float g_wh2[8 * 64 * 288];

__device__ __forceinline__ float sigf(float x) { return 1.0f / (1.0f + expf(-x)); }

// packed f32x2 helpers (sm_103a FFMA2 — PTX-only)
__device__ __forceinline__ unsigned long long splat2(float v) {
    unsigned long long d;
    asm("mov.b64 %0, {%1, %1};" : "=l"(d) : "f"(v));
    return d;
}
__device__ __forceinline__ void ffma2(unsigned long long& d, unsigned long long a, unsigned long long b) {
    asm("fma.rn.f32x2 %0, %1, %2, %0;" : "+l"(d) : "l"(a), "l"(b));
}
__device__ __forceinline__ float2 up2(unsigned long long v) {
    float2 f;
    asm("mov.b64 {%0, %1}, %2;" : "=f"(f.x), "=f"(f.y) : "l"(v));
    return f;
}

// ---------------- zero the cell states (graph replays re-run this) ---------------
__global__ void zero_c_kernel() {
    int i = blockIdx.x * blockDim.x + threadIdx.x;
    if (i < 32 * HW) g_c1[i] = 0.0f;
    if (i < 64 * HW) g_c2[i] = 0.0f;
}

// ------- weight reshape: w[4*CHID][TOTC][9], ci slice -> [coblk][ci][9][4][8] ----
template <int CHID, int TOTC, int CI0, int CIC, int CIPAD>
__global__ void reshape_kernel(const float* __restrict__ w, float* __restrict__ wr) {
    const int n = (CHID / 8) * CIPAD * 288;
    for (int i = blockIdx.x * blockDim.x + threadIdx.x; i < n; i += gridDim.x * blockDim.x) {
        int co   = i & 7;
        int g    = (i >> 3) & 3;
        int tap  = (i >> 5) % 9;
        int rest = i / 288;
        int ci   = rest % CIPAD;
        int cb   = rest / CIPAD;
        float v = 0.0f;
        if (ci < CIC) v = w[((g * CHID + cb * 8 + co) * TOTC + CI0 + ci) * 9 + tap];
        wr[i] = v;
    }
}

// ---------------- unified COB=8 conv core (f32x2 packed) -------------------------
// 128 threads; tile ROWS rows x 64 cols x 8 co (x4 gates); per-thread PXT=ROWS px.
// LSTM: gates = acc + z(zio); update c,h.  !LSTM: out(zout) = acc + bias.
template <int CINR, int NCHUNK, int CHID, int ROWS, bool LSTM>
__device__ __forceinline__ void core8(
    const float* __restrict__ x,
    const float* __restrict__ zio,     // LSTM: z input
    const float* __restrict__ bias,    // !LSTM: bias
    float* __restrict__ out,           // LSTM: hout ; !LSTM: z out
    float* __restrict__ cst,           // LSTM: cell state
    const float* __restrict__ wr, int blk, float* smem)
{
    constexpr int PXT    = ROWS;
    constexpr int ROWBLK = 64 / ROWS;
    constexpr int GPR    = 64 / PXT;
    constexpr int PS     = 8 * (ROWS + 2) * 68;

    float (*psm)[ROWS + 2][68] = (float(*)[ROWS + 2][68])smem;
    float (*wsm)[9][4][8]      = (float(*)[9][4][8])(smem + PS);

    const int tid     = threadIdx.x;
    const int co_half = tid >> 6;
    const int pid     = tid & 63;
    const int row     = pid / GPR;
    const int x0      = (pid % GPR) * PXT;

    const int co_blk = blk / ROWBLK;
    const int y0     = (blk % ROWBLK) * ROWS;

    unsigned long long acc[4][2][PXT];
    #pragma unroll
    for (int g = 0; g < 4; g++)
        #pragma unroll
        for (int p = 0; p < 2; p++)
            #pragma unroll
            for (int j = 0; j < PXT; j++) acc[g][p][j] = 0ull;

    const float* wblk = wr + (size_t)co_blk * (NCHUNK * 2304);

    for (int ch = 0; ch < NCHUNK; ch++) {
        {
            const float* src = wblk + ch * 2304;
            float* dst = &wsm[0][0][0][0];
            #pragma unroll
            for (int k = 0; k < 18; k++) dst[tid + k * 128] = src[tid + k * 128];
        }
        constexpr int NST = 8 * (ROWS + 2) * 66;
        for (int i = tid; i < NST; i += 128) {
            int col = i % 66;
            int r   = (i / 66) % (ROWS + 2);
            int ci  = i / (66 * (ROWS + 2));
            int cig = ch * 8 + ci;
            int y   = y0 - 1 + r;
            int xx  = col - 1;
            float v = 0.0f;
            if (cig < CINR && (unsigned)y < HH && (unsigned)xx < WW)
                v = x[(size_t)cig * HW + y * WW + xx];
            psm[ci][r][col] = v;
        }
        __syncthreads();

        #pragma unroll
        for (int ci = 0; ci < 8; ci++) {
            #pragma unroll
            for (int ky = 0; ky < 3; ky++) {
                unsigned long long sp[PXT + 2];
                #pragma unroll
                for (int c2 = 0; c2 < PXT + 2; c2++)
                    sp[c2] = splat2(psm[ci][row + ky][x0 + c2]);
                #pragma unroll
                for (int kx = 0; kx < 3; kx++) {
                    #pragma unroll
                    for (int g = 0; g < 4; g++) {
                        const ulonglong2 wp =
                            *(const ulonglong2*)&wsm[ci][ky * 3 + kx][g][co_half * 4];
                        #pragma unroll
                        for (int j = 0; j < PXT; j++) {
                            ffma2(acc[g][0][j], wp.x, sp[kx + j]);
                            ffma2(acc[g][1][j], wp.y, sp[kx + j]);
                        }
                    }
                }
            }
        }
        __syncthreads();
    }

    const int pos = (y0 + row) * WW + x0;

    if constexpr (!LSTM) {
        #pragma unroll
        for (int g = 0; g < 4; g++)
            #pragma unroll
            for (int cl = 0; cl < 4; cl++) {
                const int co  = co_blk * 8 + co_half * 4 + cl;
                const int chn = g * CHID + co;
                const float bv = bias[chn];
                float vals[PXT];
                #pragma unroll
                for (int j = 0; j < PXT; j++) {
                    float2 f = up2(acc[g][cl >> 1][j]);
                    vals[j] = ((cl & 1) ? f.y : f.x) + bv;
                }
                float* dst = out + (size_t)chn * HW + pos;
                if constexpr (PXT == 4)
                    *(float4*)dst = make_float4(vals[0], vals[1], vals[2], vals[3]);
                else
                    *(float2*)dst = make_float2(vals[0], vals[1]);
            }
    } else {
        #pragma unroll
        for (int cl = 0; cl < 4; cl++) {
            const int co = co_blk * 8 + co_half * 4 + cl;
            float gv[4][PXT];
            #pragma unroll
            for (int g = 0; g < 4; g++) {
                const float* zp = zio + ((size_t)g * CHID + co) * HW + pos;
                float zl[PXT];
                if constexpr (PXT == 4) {
                    float4 v = *(const float4*)zp;
                    zl[0] = v.x; zl[1] = v.y; zl[2] = v.z; zl[3] = v.w;
                } else {
                    float2 v = *(const float2*)zp;
                    zl[0] = v.x; zl[1] = v.y;
                }
                #pragma unroll
                for (int j = 0; j < PXT; j++) {
                    float2 f = up2(acc[g][cl >> 1][j]);
                    gv[g][j] = ((cl & 1) ? f.y : f.x) + zl[j];
                }
            }
            float* cp = cst + (size_t)co * HW + pos;
            float* hp = out + (size_t)co * HW + pos;
            float cold[PXT];
            if constexpr (PXT == 4) {
                float4 v = *(const float4*)cp;
                cold[0] = v.x; cold[1] = v.y; cold[2] = v.z; cold[3] = v.w;
            } else {
                float2 v = *(const float2*)cp;
                cold[0] = v.x; cold[1] = v.y;
            }
            float cv[PXT], hv[PXT];
            #pragma unroll
            for (int j = 0; j < PXT; j++) {
                float iv = sigf(gv[0][j]);
                float fv = sigf(gv[1][j]);
                float ov = sigf(gv[2][j]);
                float gg = tanhf(gv[3][j]);
                float cn = fv * cold[j] + iv * gg;
                cv[j] = cn;
                hv[j] = ov * tanhf(cn);
            }
            if constexpr (PXT == 4) {
                *(float4*)cp = make_float4(cv[0], cv[1], cv[2], cv[3]);
                *(float4*)hp = make_float4(hv[0], hv[1], hv[2], hv[3]);
            } else {
                *(float2*)cp = make_float2(cv[0], cv[1]);
                *(float2*)hp = make_float2(hv[0], hv[1]);
            }
        }
    }
}

// ---------------- batched layer-1 x-part over all T (blockIdx.z = t) -------------
__global__ void __launch_bounds__(128) zx1_kernel(
    const float* __restrict__ input, const float* __restrict__ b1)
{
    __shared__ __align__(16) float smem[8 * 6 * 68 + 2304];
    core8<3, 1, 32, 4, false>(input + (size_t)blockIdx.z * 3 * HW,
                              nullptr, b1,
                              g_z1 + (size_t)blockIdx.z * 128 * HW,
                              nullptr, g_wx1, blockIdx.x, smem);
}

// ---------------- per-slot fat kernel: 3-stage pipeline --------------------------
// blocks [0,64):   A = L1 h-step t          (4 chunks, 4-px)
// blocks [64,192): B = L2 x-conv step t-1   (4 chunks, 4-px) -> z2 ring
// blocks [192,448):C = L2 h-step t-2 + LSTM (8 chunks, 2-px)
__global__ void __launch_bounds__(128) slot_kernel(const float* __restrict__ b2, int t) {
    __shared__ __align__(16) float smem[8 * 6 * 68 + 2304];
    const int b = blockIdx.x;
    if (b < 64) {
        if (t >= TT) return;
        const float* hin = t ? g_ys1 + (size_t)(t - 1) * 32 * HW : g_zero;
        core8<32, 4, 32, 4, true>(hin, g_z1 + (size_t)t * 128 * HW, nullptr,
                                  g_ys1 + (size_t)t * 32 * HW, g_c1, g_wh1, b, smem);
    } else if (b < 192) {
        const int s = t - 1;
        if (s < 0 || s >= TT) return;
        core8<32, 4, 64, 4, false>(g_ys1 + (size_t)s * 32 * HW, nullptr, b2,
                                   g_z2r + (size_t)(s & 3) * 256 * HW,
                                   nullptr, g_wx2, b - 64, smem);
    } else {
        const int s = t - 2;
        if (s < 0 || s >= TT) return;
        const float* hin = s ? g_ys2 + (size_t)(s - 1) * 64 * HW : g_zero;
        core8<64, 8, 64, 2, true>(hin, g_z2r + (size_t)(s & 3) * 256 * HW, nullptr,
                                  g_ys2 + (size_t)s * 64 * HW, g_c2, g_wh2, b - 192, smem);
    }
}

// ---------------- FC head --------------------------------------------------------
__global__ void fc_kernel(const float* __restrict__ ys2, const float* __restrict__ fcw,
                          const float* __restrict__ fcb, float* __restrict__ out) {
    const int t = blockIdx.y;
    const int j = blockIdx.x;
    const float* a = ys2 + (size_t)t * 64 * HW;
    const float* w = fcw + (size_t)j * 64 * HW;
    float s = 0.0f;
    const int n = 64 * HW;
    for (int i = threadIdx.x * 4; i < n; i += blockDim.x * 4) {
        float4 av = *(const float4*)(a + i);
        float4 bv = *(const float4*)(w + i);
        s += av.x * bv.x + av.y * bv.y + av.z * bv.z + av.w * bv.w;
    }
    __shared__ float red[32];
    for (int off = 16; off; off >>= 1) s += __shfl_down_sync(0xffffffffu, s, off);
    if ((threadIdx.x & 31) == 0) red[threadIdx.x >> 5] = s;
    __syncthreads();
    if (threadIdx.x < 32) {
        s = (threadIdx.x < (blockDim.x >> 5)) ? red[threadIdx.x] : 0.0f;
        for (int off = 16; off; off >>= 1) s += __shfl_down_sync(0xffffffffu, s, off);
        if (threadIdx.x == 0) out[t * 6 + j] = s + fcb[j];
    }
}

// ---------------- final state copy-out -------------------------------------------
__global__ void copy_out_kernel(float* __restrict__ out) {
    const int i = blockIdx.x * blockDim.x + threadIdx.x;
    float* o = out + TT * 6;
    if (i < 32 * HW) {
        o[i]           = g_ys1[127 * 32 * HW + i];
        o[32 * HW + i] = g_c1[i];
    }
    if (i < 64 * HW) {
        o[64 * HW + i]           = g_ys2[(size_t)127 * 64 * HW + i];
        o[64 * HW + 64 * HW + i] = g_c2[i];
    }
}

// ---------------- launch (single stream, no stream/event objects) ----------------
extern "C" void kernel_launch(void* const* d_in, const int* in_sizes, int n_in,
                              void* d_out, int out_size) {
    const float* input = (const float*)d_in[0];
    const float* w1    = (const float*)d_in[1];
    const float* b1    = (const float*)d_in[2];
    const float* w2    = (const float*)d_in[3];
    const float* b2    = (const float*)d_in[4];
    const float* fcw   = (const float*)d_in[5];
    const float* fcb   = (const float*)d_in[6];
    float* out = (float*)d_out;

    float *ys2, *wx1, *wh1, *wx2, *wh2;
    cudaGetSymbolAddress((void**)&ys2, g_ys2);
    cudaGetSymbolAddress((void**)&wx1, g_wx1);
    cudaGetSymbolAddress((void**)&wh1, g_wh1);
    cudaGetSymbolAddress((void**)&wx2, g_wx2);
    cudaGetSymbolAddress((void**)&wh2, g_wh2);

    zero_c_kernel<<<1024, 256>>>();
    reshape_kernel<32, 35, 0,  3,  8 ><<<32,  256>>>(w1, wx1);
    reshape_kernel<32, 35, 3,  32, 32><<<128, 256>>>(w1, wh1);
    reshape_kernel<64, 96, 0,  32, 32><<<256, 256>>>(w2, wx2);
    reshape_kernel<64, 96, 32, 64, 64><<<512, 256>>>(w2, wh2);

    // layer-1 x-part for all T (batched): 4 co-blk x 16 row-blk
    zx1_kernel<<<dim3(64, 1, TT), 128>>>(input, b1);

    // 3-stage pipelined slots
    for (int t = 0; t <= TT + 1; t++)
        slot_kernel<<<448, 128>>>(b2, t);

    dim3 fg(6, TT);
    fc_kernel<<<fg, 256>>>(ys2, fcw, fcb, out);
    copy_out_kernel<<<1024, 256>>>(out);
}

// round 8
// speedup vs baseline: 3.5969x; 1.0227x over previous
#include <cuda_runtime.h>
#include <math.h>

#define TT 128
#define HH 64
#define WW 64
#define HW 4096

// ---------------- scratch (device globals: allocation-free rule) ----------------
__device__ float g_ys1[TT * 32 * HW];           // layer-1 hidden sequence
__device__ float g_ys2[TT * 64 * HW];           // layer-2 hidden sequence
__device__ float g_z1 [TT * 128 * HW];          // layer-1 x-part preactivations
__device__ float g_z2r[4 * 256 * HW];           // layer-2 x-part ring (4 steps)
__device__ float g_c1[32 * HW];
__device__ float g_c2[64 * HW];
__device__ float g_zero[64 * HW];               // zero at load, never written
__device__ float g_wx1[4 * 8  * 288];           // [coblk][ci][9][4][8]
__device__ float g_wh1[4 * 32 * 288];
__device__ float g_wx2[8 * 32 * 288];
__device__ float g_wh2[8 * 64 * 288];
__device__ int   g_cntA[TT], g_cntB[TT], g_cntC[TT];   // pipeline flags

__device__ __forceinline__ float sigf(float x) { return 1.0f / (1.0f + expf(-x)); }

// packed f32x2 helpers (sm_103a FFMA2 — PTX-only)
__device__ __forceinline__ unsigned long long splat2(float v) {
    unsigned long long d;
    asm("mov.b64 %0, {%1, %1};" : "=l"(d) : "f"(v));
    return d;
}
__device__ __forceinline__ void ffma2(unsigned long long& d, unsigned long long a, unsigned long long b) {
    asm("fma.rn.f32x2 %0, %1, %2, %0;" : "+l"(d) : "l"(a), "l"(b));
}
__device__ __forceinline__ float2 up2(unsigned long long v) {
    float2 f;
    asm("mov.b64 {%0, %1}, %2;" : "=f"(f.x), "=f"(f.y) : "l"(v));
    return f;
}

// ---------------- flag sync (persistent-kernel pipeline) -------------------------
__device__ __forceinline__ void waitfor(const int* cnt, int target) {
    if (threadIdx.x == 0) {
        while (*(volatile const int*)cnt < target) __nanosleep(64);
        __threadfence();
    }
    __syncthreads();
}
__device__ __forceinline__ void arrive(int* cnt) {
    __threadfence();
    __syncthreads();
    if (threadIdx.x == 0) atomicAdd(cnt, 1);
}

// ---------------- zero states + flags (graph replays re-run this) ----------------
__global__ void zero_c_kernel() {
    int i = blockIdx.x * blockDim.x + threadIdx.x;
    if (i < 32 * HW) g_c1[i] = 0.0f;
    if (i < 64 * HW) g_c2[i] = 0.0f;
    if (i < TT) { g_cntA[i] = 0; g_cntB[i] = 0; g_cntC[i] = 0; }
}

// ------- weight reshape: w[4*CHID][TOTC][9], ci slice -> [coblk][ci][9][4][8] ----
template <int CHID, int TOTC, int CI0, int CIC, int CIPAD>
__global__ void reshape_kernel(const float* __restrict__ w, float* __restrict__ wr) {
    const int n = (CHID / 8) * CIPAD * 288;
    for (int i = blockIdx.x * blockDim.x + threadIdx.x; i < n; i += gridDim.x * blockDim.x) {
        int co   = i & 7;
        int g    = (i >> 3) & 3;
        int tap  = (i >> 5) % 9;
        int rest = i / 288;
        int ci   = rest % CIPAD;
        int cb   = rest / CIPAD;
        float v = 0.0f;
        if (ci < CIC) v = w[((g * CHID + cb * 8 + co) * TOTC + CI0 + ci) * 9 + tap];
        wr[i] = v;
    }
}

// ---------------- unified COB=8 conv core (f32x2 packed) -------------------------
// 128 threads; tile ROWS rows x 64 cols x 8 co (x4 gates); per-thread PXT=ROWS px.
// LSTM: gates = acc + z(zio); update c,h.  !LSTM: out = acc + bias.
// ZCG: load z via __ldcg (L2) — required for ring-buffer reuse (L1 staleness).
template <int CINR, int NCHUNK, int CHID, int ROWS, bool LSTM, bool ZCG>
__device__ __forceinline__ void core8(
    const float* __restrict__ x,
    const float* __restrict__ zio,
    const float* __restrict__ bias,
    float* __restrict__ out,
    float* __restrict__ cst,
    const float* __restrict__ wr, int blk, float* smem)
{
    constexpr int PXT    = ROWS;
    constexpr int ROWBLK = 64 / ROWS;
    constexpr int GPR    = 64 / PXT;
    constexpr int PS     = 8 * (ROWS + 2) * 68;

    float (*psm)[ROWS + 2][68] = (float(*)[ROWS + 2][68])smem;
    float (*wsm)[9][4][8]      = (float(*)[9][4][8])(smem + PS);

    const int tid     = threadIdx.x;
    const int co_half = tid >> 6;
    const int pid     = tid & 63;
    const int row     = pid / GPR;
    const int x0      = (pid % GPR) * PXT;

    const int co_blk = blk / ROWBLK;
    const int y0     = (blk % ROWBLK) * ROWS;

    unsigned long long acc[4][2][PXT];
    #pragma unroll
    for (int g = 0; g < 4; g++)
        #pragma unroll
        for (int p = 0; p < 2; p++)
            #pragma unroll
            for (int j = 0; j < PXT; j++) acc[g][p][j] = 0ull;

    const float* wblk = wr + (size_t)co_blk * (NCHUNK * 2304);

    for (int ch = 0; ch < NCHUNK; ch++) {
        {
            const float* src = wblk + ch * 2304;
            float* dst = &wsm[0][0][0][0];
            #pragma unroll
            for (int k = 0; k < 18; k++) dst[tid + k * 128] = src[tid + k * 128];
        }
        constexpr int NST = 8 * (ROWS + 2) * 66;
        for (int i = tid; i < NST; i += 128) {
            int col = i % 66;
            int r   = (i / 66) % (ROWS + 2);
            int ci  = i / (66 * (ROWS + 2));
            int cig = ch * 8 + ci;
            int y   = y0 - 1 + r;
            int xx  = col - 1;
            float v = 0.0f;
            if (cig < CINR && (unsigned)y < HH && (unsigned)xx < WW)
                v = x[(size_t)cig * HW + y * WW + xx];
            psm[ci][r][col] = v;
        }
        __syncthreads();

        #pragma unroll
        for (int ci = 0; ci < 8; ci++) {
            #pragma unroll
            for (int ky = 0; ky < 3; ky++) {
                unsigned long long sp[PXT + 2];
                #pragma unroll
                for (int c2 = 0; c2 < PXT + 2; c2++)
                    sp[c2] = splat2(psm[ci][row + ky][x0 + c2]);
                #pragma unroll
                for (int kx = 0; kx < 3; kx++) {
                    #pragma unroll
                    for (int g = 0; g < 4; g++) {
                        const ulonglong2 wp =
                            *(const ulonglong2*)&wsm[ci][ky * 3 + kx][g][co_half * 4];
                        #pragma unroll
                        for (int j = 0; j < PXT; j++) {
                            ffma2(acc[g][0][j], wp.x, sp[kx + j]);
                            ffma2(acc[g][1][j], wp.y, sp[kx + j]);
                        }
                    }
                }
            }
        }
        __syncthreads();
    }

    const int pos = (y0 + row) * WW + x0;

    if constexpr (!LSTM) {
        #pragma unroll
        for (int g = 0; g < 4; g++)
            #pragma unroll
            for (int cl = 0; cl < 4; cl++) {
                const int co  = co_blk * 8 + co_half * 4 + cl;
                const int chn = g * CHID + co;
                const float bv = bias[chn];
                float vals[PXT];
                #pragma unroll
                for (int j = 0; j < PXT; j++) {
                    float2 f = up2(acc[g][cl >> 1][j]);
                    vals[j] = ((cl & 1) ? f.y : f.x) + bv;
                }
                float* dst = out + (size_t)chn * HW + pos;
                if constexpr (PXT == 4)
                    *(float4*)dst = make_float4(vals[0], vals[1], vals[2], vals[3]);
                else
                    *(float2*)dst = make_float2(vals[0], vals[1]);
            }
    } else {
        #pragma unroll
        for (int cl = 0; cl < 4; cl++) {
            const int co = co_blk * 8 + co_half * 4 + cl;
            float gv[4][PXT];
            #pragma unroll
            for (int g = 0; g < 4; g++) {
                const float* zp = zio + ((size_t)g * CHID + co) * HW + pos;
                float zl[PXT];
                if constexpr (PXT == 4) {
                    float4 v = ZCG ? __ldcg((const float4*)zp) : *(const float4*)zp;
                    zl[0] = v.x; zl[1] = v.y; zl[2] = v.z; zl[3] = v.w;
                } else {
                    float2 v = ZCG ? __ldcg((const float2*)zp) : *(const float2*)zp;
                    zl[0] = v.x; zl[1] = v.y;
                }
                #pragma unroll
                for (int j = 0; j < PXT; j++) {
                    float2 f = up2(acc[g][cl >> 1][j]);
                    gv[g][j] = ((cl & 1) ? f.y : f.x) + zl[j];
                }
            }
            float* cp = cst + (size_t)co * HW + pos;
            float* hp = out + (size_t)co * HW + pos;
            float cold[PXT];
            if constexpr (PXT == 4) {
                float4 v = *(const float4*)cp;
                cold[0] = v.x; cold[1] = v.y; cold[2] = v.z; cold[3] = v.w;
            } else {
                float2 v = *(const float2*)cp;
                cold[0] = v.x; cold[1] = v.y;
            }
            float cv[PXT], hv[PXT];
            #pragma unroll
            for (int j = 0; j < PXT; j++) {
                float iv = sigf(gv[0][j]);
                float fv = sigf(gv[1][j]);
                float ov = sigf(gv[2][j]);
                float gg = tanhf(gv[3][j]);
                float cn = fv * cold[j] + iv * gg;
                cv[j] = cn;
                hv[j] = ov * tanhf(cn);
            }
            if constexpr (PXT == 4) {
                *(float4*)cp = make_float4(cv[0], cv[1], cv[2], cv[3]);
                *(float4*)hp = make_float4(hv[0], hv[1], hv[2], hv[3]);
            } else {
                *(float2*)cp = make_float2(cv[0], cv[1]);
                *(float2*)hp = make_float2(hv[0], hv[1]);
            }
        }
    }
}

// ---------------- batched layer-1 x-part over all T (blockIdx.z = t) -------------
__global__ void __launch_bounds__(128) zx1_kernel(
    const float* __restrict__ input, const float* __restrict__ b1)
{
    __shared__ __align__(16) float smem[8 * 6 * 68 + 2304];
    core8<3, 1, 32, 4, false, false>(input + (size_t)blockIdx.z * 3 * HW,
                                     nullptr, b1,
                                     g_z1 + (size_t)blockIdx.z * 128 * HW,
                                     nullptr, g_wx1, blockIdx.x, smem);
}

// ---------------- persistent pipeline kernel -------------------------------------
// blocks [0,64):   A chain: L1 h-step t           (4 chunks, 4-px)
// blocks [64,192): B chain: L2 x-conv step s       (4 chunks, 4-px) -> z2 ring
// blocks [192,448):C chain: L2 h-step s + LSTM     (8 chunks, 2-px)
// All 448 blocks co-resident: __launch_bounds__(128,4) -> 4 blocks/SM (592 >= 448).
__global__ void __launch_bounds__(128, 4) persist_kernel(const float* __restrict__ b2) {
    __shared__ __align__(16) float smem[8 * 6 * 68 + 2304];
    const int b = blockIdx.x;
    if (b < 64) {
        for (int t = 0; t < TT; t++) {
            if (t) waitfor(&g_cntA[t - 1], 64);
            const float* hin = t ? g_ys1 + (size_t)(t - 1) * 32 * HW : g_zero;
            core8<32, 4, 32, 4, true, false>(hin, g_z1 + (size_t)t * 128 * HW, nullptr,
                                             g_ys1 + (size_t)t * 32 * HW, g_c1, g_wh1, b, smem);
            arrive(&g_cntA[t]);
        }
    } else if (b < 192) {
        const int bb = b - 64;
        for (int s = 0; s < TT; s++) {
            waitfor(&g_cntA[s], 64);
            if (s >= 4) waitfor(&g_cntC[s - 4], 256);      // ring slot reuse
            core8<32, 4, 64, 4, false, false>(g_ys1 + (size_t)s * 32 * HW, nullptr, b2,
                                              g_z2r + (size_t)(s & 3) * 256 * HW,
                                              nullptr, g_wx2, bb, smem);
            arrive(&g_cntB[s]);
        }
    } else {
        const int bb = b - 192;
        for (int s = 0; s < TT; s++) {
            waitfor(&g_cntB[s], 128);
            if (s) waitfor(&g_cntC[s - 1], 256);
            const float* hin = s ? g_ys2 + (size_t)(s - 1) * 64 * HW : g_zero;
            core8<64, 8, 64, 2, true, true>(hin, g_z2r + (size_t)(s & 3) * 256 * HW, nullptr,
                                            g_ys2 + (size_t)s * 64 * HW, g_c2, g_wh2, bb, smem);
            arrive(&g_cntC[s]);
        }
    }
}

// ---------------- FC head --------------------------------------------------------
__global__ void fc_kernel(const float* __restrict__ ys2, const float* __restrict__ fcw,
                          const float* __restrict__ fcb, float* __restrict__ out) {
    const int t = blockIdx.y;
    const int j = blockIdx.x;
    const float* a = ys2 + (size_t)t * 64 * HW;
    const float* w = fcw + (size_t)j * 64 * HW;
    float s = 0.0f;
    const int n = 64 * HW;
    for (int i = threadIdx.x * 4; i < n; i += blockDim.x * 4) {
        float4 av = *(const float4*)(a + i);
        float4 bv = *(const float4*)(w + i);
        s += av.x * bv.x + av.y * bv.y + av.z * bv.z + av.w * bv.w;
    }
    __shared__ float red[32];
    for (int off = 16; off; off >>= 1) s += __shfl_down_sync(0xffffffffu, s, off);
    if ((threadIdx.x & 31) == 0) red[threadIdx.x >> 5] = s;
    __syncthreads();
    if (threadIdx.x < 32) {
        s = (threadIdx.x < (blockDim.x >> 5)) ? red[threadIdx.x] : 0.0f;
        for (int off = 16; off; off >>= 1) s += __shfl_down_sync(0xffffffffu, s, off);
        if (threadIdx.x == 0) out[t * 6 + j] = s + fcb[j];
    }
}

// ---------------- final state copy-out -------------------------------------------
__global__ void copy_out_kernel(float* __restrict__ out) {
    const int i = blockIdx.x * blockDim.x + threadIdx.x;
    float* o = out + TT * 6;
    if (i < 32 * HW) {
        o[i]           = g_ys1[127 * 32 * HW + i];
        o[32 * HW + i] = g_c1[i];
    }
    if (i < 64 * HW) {
        o[64 * HW + i]           = g_ys2[(size_t)127 * 64 * HW + i];
        o[64 * HW + 64 * HW + i] = g_c2[i];
    }
}

// ---------------- launch (single stream, no stream/event objects) ----------------
extern "C" void kernel_launch(void* const* d_in, const int* in_sizes, int n_in,
                              void* d_out, int out_size) {
    const float* input = (const float*)d_in[0];
    const float* w1    = (const float*)d_in[1];
    const float* b1    = (const float*)d_in[2];
    const float* w2    = (const float*)d_in[3];
    const float* b2    = (const float*)d_in[4];
    const float* fcw   = (const float*)d_in[5];
    const float* fcb   = (const float*)d_in[6];
    float* out = (float*)d_out;

    float *ys2, *wx1, *wh1, *wx2, *wh2;
    cudaGetSymbolAddress((void**)&ys2, g_ys2);
    cudaGetSymbolAddress((void**)&wx1, g_wx1);
    cudaGetSymbolAddress((void**)&wh1, g_wh1);
    cudaGetSymbolAddress((void**)&wx2, g_wx2);
    cudaGetSymbolAddress((void**)&wh2, g_wh2);

    zero_c_kernel<<<1024, 256>>>();
    reshape_kernel<32, 35, 0,  3,  8 ><<<32,  256>>>(w1, wx1);
    reshape_kernel<32, 35, 3,  32, 32><<<128, 256>>>(w1, wh1);
    reshape_kernel<64, 96, 0,  32, 32><<<256, 256>>>(w2, wx2);
    reshape_kernel<64, 96, 32, 64, 64><<<512, 256>>>(w2, wh2);

    // layer-1 x-part for all T (batched): 4 co-blk x 16 row-blk
    zx1_kernel<<<dim3(64, 1, TT), 128>>>(input, b1);

    // all 128 timesteps, both layers: one persistent flag-synced pipeline
    persist_kernel<<<448, 128>>>(b2);

    dim3 fg(6, TT);
    fc_kernel<<<fg, 256>>>(ys2, fcw, fcb, out);
    copy_out_kernel<<<1024, 256>>>(out);
}